// round 11
// baseline (speedup 1.0000x reference)
#include <cuda_runtime.h>
#include <cstdint>

#define VS 100
#define BATCH 8
#define NUM_COORDS 65536
#define NPTS (BATCH * NUM_COORDS)          // 524288
#define NCELLS (BATCH * VS * VS * VS)      // 8,000,000
#define NF4 (NCELLS * 10 / 4)              // 20,000,000 float4s of output

// Scratch: zero-initialized at module load. occupied_kernel re-zeroes the
// cells it consumes and reset_kernel clears the worklist counter, so every
// graph replay starts from the same state.
// g_sum ch0..5 = sums(x,y,z,f0,f1,f2), ch6 = count (election), ch7 = 0.
__device__ float g_sum[(size_t)NCELLS * 8];   // 256 MB
__device__ int   g_list[NPTS];                // 2 MB worklist of occupied cells
__device__ int   g_count;                     // worklist size

// ---------------------------------------------------------------------------
// 1) Background pattern writer: the whole 320 MB output, no loads.
//    Record = [m0..m5, i*.01, j*.01, k*.01, occ]; background = zeros + index
//    grid + occ=0. Two cells = 20 floats = 5 float4s; thread handles one f4.
__global__ void __launch_bounds__(256) stream_kernel(float4* __restrict__ out4)
{
    int F = blockIdx.x * 256 + threadIdx.x;   // < NF4 (grid exact)
    int G = F / 5;                            // 2-cell chunk id
    int m = F - G * 5;                        // position within chunk
    int cell = 2 * G + (m == 4 ? 1 : 0);      // which cell this f4 touches

    // Decode (i, j, k) within the batch's 100^3 block.
    int k = cell % VS;
    int t = cell / VS;
    int j = t % VS;
    int i = (t / VS) % VS;
    float fi = (float)i * 0.01f;
    float fj = (float)j * 0.01f;
    float fk = (float)k * 0.01f;

    float4 v = make_float4(0.f, 0.f, 0.f, 0.f);
    if (m == 1) { v.z = fi; v.w = fj; }           // floats 4-7 of cell0
    else if (m == 2) { v.x = fk; }                // floats 8-11: k0,occ0,m0,m1
    else if (m == 4) { v.x = fi; v.y = fj; v.z = fk; }  // floats 16-19 of cell1

    out4[F] = v;
}

// ---------------------------------------------------------------------------
// 2) Scatter with first-writer election -> worklist.
__global__ void __launch_bounds__(256) scatter_kernel(
    const float* __restrict__ coords,
    const float* __restrict__ feats)
{
    int idx = blockIdx.x * blockDim.x + threadIdx.x;
    if (idx >= NPTS) return;

    float x = coords[idx * 3 + 0];
    float y = coords[idx * 3 + 1];
    float z = coords[idx * 3 + 2];

    // Reference constants collapse in f32: res = denom = 0.01f, shift = -0.01f
    const float shift = 0.01f;
    const float denom = 0.01f;
    int ix = (int)floorf((x + shift) / denom);
    int iy = (int)floorf((y + shift) / denom);
    int iz = (int)floorf((z + shift) / denom);

    if (ix < 1 || ix > VS || iy < 1 || iy > VS || iz < 1 || iz > VS) return;

    int b = idx >> 16;  // NUM_COORDS = 65536
    int cell = ((b * VS + (ix - 1)) * VS + (iy - 1)) * VS + (iz - 1);

    float f0 = feats[idx * 3 + 0];
    float f1 = feats[idx * 3 + 1];
    float f2 = feats[idx * 3 + 2];

    float* s = &g_sum[(size_t)cell * 8];
    asm volatile("red.global.add.v4.f32 [%0], {%1, %2, %3, %4};"
                 :: "l"(s), "f"(x), "f"(y), "f"(z), "f"(f0) : "memory");
    asm volatile("red.global.add.v2.f32 [%0], {%1, %2};"
                 :: "l"(s + 4), "f"(f1), "f"(f2) : "memory");
    // Count + first-writer election (exact: integers accumulate exactly).
    float old = atomicAdd(s + 6, 1.0f);
    if (old == 0.0f) {
        int pos = atomicAdd(&g_count, 1);
        g_list[pos] = cell;
    }
}

// ---------------------------------------------------------------------------
// 3) Occupied cells only: scatter means into the pre-written background.
__global__ void __launch_bounds__(256) occupied_kernel(float* __restrict__ out)
{
    int idx = blockIdx.x * 256 + threadIdx.x;
    if (idx >= g_count) return;

    int cell = g_list[idx];
    float4* sp = (float4*)&g_sum[(size_t)cell * 8];
    float4 a  = sp[0];
    float4 b4 = sp[1];
    float cnt = b4.z;

    float* o = out + (size_t)cell * 10;
    ((float2*)o)[0] = make_float2(a.x / cnt, a.y / cnt);
    ((float2*)o)[1] = make_float2(a.z / cnt, a.w / cnt);
    ((float2*)o)[2] = make_float2(b4.x / cnt, b4.y / cnt);
    o[9] = 1.0f;   // occupied

    // Self-clean scratch for the next graph replay.
    float4 z4 = make_float4(0.f, 0.f, 0.f, 0.f);
    sp[0] = z4;
    sp[1] = z4;
}

// 4) Reset worklist counter for the next replay.
__global__ void reset_kernel() { g_count = 0; }

// ---------------------------------------------------------------------------
extern "C" void kernel_launch(void* const* d_in, const int* in_sizes, int n_in,
                              void* d_out, int out_size)
{
    const float* coords = (const float*)d_in[0];
    const float* feats  = (const float*)d_in[1];
    float* out = (float*)d_out;

    // Fork: stream_kernel (input-independent 320 MB write) runs concurrently
    // with scatter_kernel; occupied_kernel joins both.
    cudaStream_t s2;
    cudaStreamCreateWithFlags(&s2, cudaStreamNonBlocking);
    cudaEvent_t eFork, eJoin;
    cudaEventCreateWithFlags(&eFork, cudaEventDisableTiming);
    cudaEventCreateWithFlags(&eJoin, cudaEventDisableTiming);

    cudaEventRecord(eFork, 0);
    cudaStreamWaitEvent(s2, eFork, 0);
    stream_kernel<<<NF4 / 256, 256, 0, s2>>>((float4*)out);  // 78125 blocks
    cudaEventRecord(eJoin, s2);

    scatter_kernel<<<NPTS / 256, 256>>>(coords, feats);      // 2048 blocks

    cudaStreamWaitEvent(0, eJoin, 0);
    occupied_kernel<<<NPTS / 256, 256>>>(out);               // covers worst case
    reset_kernel<<<1, 1>>>();
}